// round 1
// baseline (speedup 1.0000x reference)
#include <cuda_runtime.h>
#include <math.h>

#define NB 2
#define NS 2048
#define ND 768
#define NH 12
#define NHD 64
#define NQKV 2304
#define NROWS 4096   // NB*NS

#define NEG_BIG (-1e30f)
#define PAD 68

// Scratch (device globals: allocation-free per harness rules)
__device__ float g_qkv[(size_t)NROWS * NQKV];   // 37.7 MB
__device__ float g_attn[(size_t)NROWS * ND];    // 12.6 MB

// ---------------------------------------------------------------------------
// SGEMM + bias: C[M,N] = A[M,K] @ W[K,N] + bias[N]
// 128x128 tile, BK=16, 256 threads, 8x8 per-thread register tile.
// M,N multiples of 128; K multiple of 16 (true for all calls here).
// ---------------------------------------------------------------------------
__global__ __launch_bounds__(256, 2)
void sgemm_bias_kernel(const float* __restrict__ A, const float* __restrict__ W,
                       const float* __restrict__ bias, float* __restrict__ C,
                       int M, int N, int K)
{
    __shared__ float As[16 * 132];   // stored transposed: As[k][row]
    __shared__ float Bs[16 * 132];   // Bs[k][col]
    const int tid  = threadIdx.x;
    const int row0 = blockIdx.y * 128;
    const int col0 = blockIdx.x * 128;
    const int tr   = (tid >> 4) * 8;
    const int tc   = (tid & 15) * 8;

    float acc[8][8];
#pragma unroll
    for (int i = 0; i < 8; i++)
#pragma unroll
        for (int j = 0; j < 8; j++) acc[i][j] = 0.f;

    for (int k0 = 0; k0 < K; k0 += 16) {
#pragma unroll
        for (int l = 0; l < 2; l++) {
            int f  = tid + l * 256;
            int ar = f >> 2;
            int ac = (f & 3) * 4;
            float4 a4 = *(const float4*)(A + (size_t)(row0 + ar) * K + k0 + ac);
            As[(ac + 0) * 132 + ar] = a4.x;
            As[(ac + 1) * 132 + ar] = a4.y;
            As[(ac + 2) * 132 + ar] = a4.z;
            As[(ac + 3) * 132 + ar] = a4.w;
            int br = f >> 5;
            int bc = (f & 31) * 4;
            *(float4*)&Bs[br * 132 + bc] =
                *(const float4*)(W + (size_t)(k0 + br) * N + col0 + bc);
        }
        __syncthreads();
#pragma unroll
        for (int kk = 0; kk < 16; kk++) {
            float a[8], b[8];
            *(float4*)&a[0] = *(const float4*)&As[kk * 132 + tr];
            *(float4*)&a[4] = *(const float4*)&As[kk * 132 + tr + 4];
            *(float4*)&b[0] = *(const float4*)&Bs[kk * 132 + tc];
            *(float4*)&b[4] = *(const float4*)&Bs[kk * 132 + tc + 4];
#pragma unroll
            for (int i = 0; i < 8; i++)
#pragma unroll
                for (int j = 0; j < 8; j++)
                    acc[i][j] = fmaf(a[i], b[j], acc[i][j]);
        }
        __syncthreads();
    }

    float bv[8];
    *(float4*)&bv[0] = *(const float4*)(bias + col0 + tc);
    *(float4*)&bv[4] = *(const float4*)(bias + col0 + tc + 4);
#pragma unroll
    for (int i = 0; i < 8; i++) {
        float* cp = C + (size_t)(row0 + tr + i) * N + col0 + tc;
        float4 o0 = make_float4(acc[i][0] + bv[0], acc[i][1] + bv[1],
                                acc[i][2] + bv[2], acc[i][3] + bv[3]);
        float4 o1 = make_float4(acc[i][4] + bv[4], acc[i][5] + bv[5],
                                acc[i][6] + bv[6], acc[i][7] + bv[7]);
        *(float4*)cp       = o0;
        *(float4*)(cp + 4) = o1;
    }
}

// ---------------------------------------------------------------------------
// RoPE in-place on q and k parts of qkv. One thread per (b,s,h,pair).
// ---------------------------------------------------------------------------
__global__ void rope_kernel(float* __restrict__ qkv, const int* __restrict__ layer_p)
{
    int idx = blockIdx.x * blockDim.x + threadIdx.x;
    if (idx >= NROWS * NH * 32) return;
    int i  = idx & 31;          // rotation pair index
    int hh = (idx >> 5) % NH;
    int bs = (idx >> 5) / NH;   // b*NS + s
    int s  = bs & (NS - 1);

    bool is_global = (layer_p[0] % 3) == 0;
    float theta = is_global ? 160000.f : 10000.f;
    float freq  = powf(theta, -(float)(2 * i) / 64.f);
    float ang   = (float)s * freq;
    float sn, cs;
    sincosf(ang, &sn, &cs);

    size_t base = (size_t)bs * NQKV + hh * NHD + 2 * i;
    float qe = qkv[base], qo = qkv[base + 1];
    qkv[base]      = qe * cs - qo * sn;
    qkv[base + 1]  = qo * cs + qe * sn;
    float ke = qkv[base + ND], ko = qkv[base + ND + 1];
    qkv[base + ND]     = ke * cs - ko * sn;
    qkv[base + ND + 1] = ko * cs + ke * sn;
}

// ---------------------------------------------------------------------------
// Flash-style banded attention. One block per (b, h, 64-row query tile).
// Local layer: key tiles qt-2..qt+2 (band |i-j|<=128). Global: all tiles.
// Q,K stored transposed [dim][row] in smem for conflict-free float4 reads.
// ---------------------------------------------------------------------------
__global__ __launch_bounds__(256, 1)
void attn_kernel(const float* __restrict__ qkv, float* __restrict__ aout,
                 const int* __restrict__ layer_p)
{
    extern __shared__ float sm[];
    float* Qt    = sm;               // [64][PAD] Qt[d*PAD+r] (pre-scaled)
    float* Ks    = Qt + 64 * PAD;    // K transposed [d][r]; reused as P[r][c]
    float* Vs    = Ks + 64 * PAD;    // V row-major [key][dim]
    float* row_m = Vs + 64 * PAD;
    float* row_l = row_m + 64;
    float* row_s = row_l + 64;

    const int tid = threadIdx.x;
    const int blk = blockIdx.x;
    const int qt  = blk & 31;
    const int hh  = (blk >> 5) % NH;
    const int b   = blk / (32 * NH);
    const bool is_global = (layer_p[0] % 3) == 0;
    const int q0 = qt * 64;

    // Load Q tile (scaled by 1/sqrt(64)) transposed
    {
        int r = tid >> 2;
        int part = tid & 3;
        const float* src = qkv + (size_t)(b * NS + q0 + r) * NQKV + hh * NHD + part * 16;
#pragma unroll
        for (int v = 0; v < 4; v++) {
            float4 q4 = *(const float4*)(src + v * 4);
            int d0 = part * 16 + v * 4;
            Qt[(d0 + 0) * PAD + r] = q4.x * 0.125f;
            Qt[(d0 + 1) * PAD + r] = q4.y * 0.125f;
            Qt[(d0 + 2) * PAD + r] = q4.z * 0.125f;
            Qt[(d0 + 3) * PAD + r] = q4.w * 0.125f;
        }
    }
    if (tid < 64) { row_m[tid] = NEG_BIG; row_l[tid] = 0.f; }

    const int tr = (tid >> 4) * 4;
    const int tc = (tid & 15) * 4;
    float acc[4][4];
#pragma unroll
    for (int i = 0; i < 4; i++)
#pragma unroll
        for (int j = 0; j < 4; j++) acc[i][j] = 0.f;

    const int kt0 = is_global ? 0 : max(0, qt - 2);
    const int kt1 = is_global ? 31 : min(31, qt + 2);

    for (int kt = kt0; kt <= kt1; kt++) {
        __syncthreads();  // prior P/V consumers done; Q/stat init done (iter 0)
        {   // load K (transposed) and V tiles
            int r = tid >> 2;
            int part = tid & 3;
            const float* ksrc = qkv + (size_t)(b * NS + kt * 64 + r) * NQKV + ND + hh * NHD + part * 16;
#pragma unroll
            for (int v = 0; v < 4; v++) {
                int d0 = part * 16 + v * 4;
                float4 k4 = *(const float4*)(ksrc + v * 4);
                Ks[(d0 + 0) * PAD + r] = k4.x;
                Ks[(d0 + 1) * PAD + r] = k4.y;
                Ks[(d0 + 2) * PAD + r] = k4.z;
                Ks[(d0 + 3) * PAD + r] = k4.w;
                *(float4*)&Vs[r * PAD + d0] = *(const float4*)(ksrc + ND + v * 4);
            }
        }
        __syncthreads();

        // S = Q K^T (4x4 per thread)
        float sv[4][4];
#pragma unroll
        for (int i = 0; i < 4; i++)
#pragma unroll
            for (int j = 0; j < 4; j++) sv[i][j] = 0.f;
#pragma unroll 8
        for (int d = 0; d < 64; d++) {
            float qa[4], kb[4];
            *(float4*)qa = *(const float4*)&Qt[d * PAD + tr];
            *(float4*)kb = *(const float4*)&Ks[d * PAD + tc];
#pragma unroll
            for (int i = 0; i < 4; i++)
#pragma unroll
                for (int j = 0; j < 4; j++)
                    sv[i][j] = fmaf(qa[i], kb[j], sv[i][j]);
        }
        if (!is_global) {
#pragma unroll
            for (int i = 0; i < 4; i++)
#pragma unroll
                for (int j = 0; j < 4; j++) {
                    int dlt = (q0 + tr + i) - (kt * 64 + tc + j);
                    if (dlt < 0) dlt = -dlt;
                    if (dlt > 128) sv[i][j] = NEG_BIG;
                }
        }
        __syncthreads();  // K fully consumed -> reuse buffer for P
#pragma unroll
        for (int i = 0; i < 4; i++)
#pragma unroll
            for (int j = 0; j < 4; j++)
                Ks[(tr + i) * PAD + tc + j] = sv[i][j];
        __syncthreads();

        // Online softmax update: 4 lanes per row, 16 entries each
        {
            int r  = tid >> 2;
            int qd = tid & 3;
            float* Pr = &Ks[r * PAD + qd * 16];
            float mloc = NEG_BIG;
#pragma unroll
            for (int c = 0; c < 16; c++) mloc = fmaxf(mloc, Pr[c]);
            mloc = fmaxf(mloc, __shfl_xor_sync(0xffffffffu, mloc, 1));
            mloc = fmaxf(mloc, __shfl_xor_sync(0xffffffffu, mloc, 2));
            float m_old = row_m[r];
            float m_new = fmaxf(m_old, mloc);
            float ls = 0.f;
#pragma unroll
            for (int c = 0; c < 16; c++) {
                float e = expf(Pr[c] - m_new);
                Pr[c] = e;
                ls += e;
            }
            ls += __shfl_xor_sync(0xffffffffu, ls, 1);
            ls += __shfl_xor_sync(0xffffffffu, ls, 2);
            if (qd == 0) {
                float fac = expf(m_old - m_new);   // 0 on first tile
                row_s[r] = fac;
                row_m[r] = m_new;
                row_l[r] = row_l[r] * fac + ls;
            }
        }
        __syncthreads();

        // Rescale accumulator, then O += P @ V
        {
            float fac[4];
#pragma unroll
            for (int i = 0; i < 4; i++) fac[i] = row_s[tr + i];
#pragma unroll
            for (int i = 0; i < 4; i++)
#pragma unroll
                for (int j = 0; j < 4; j++) acc[i][j] *= fac[i];
#pragma unroll 8
            for (int c = 0; c < 64; c++) {
                float vv[4], pp[4];
                *(float4*)vv = *(const float4*)&Vs[c * PAD + tc];
#pragma unroll
                for (int i = 0; i < 4; i++) pp[i] = Ks[(tr + i) * PAD + c];
#pragma unroll
                for (int i = 0; i < 4; i++)
#pragma unroll
                    for (int j = 0; j < 4; j++)
                        acc[i][j] = fmaf(pp[i], vv[j], acc[i][j]);
            }
        }
    }

    // Normalize and write out [b*NS+s][h*64+d]
#pragma unroll
    for (int i = 0; i < 4; i++) {
        float inv = 1.f / row_l[tr + i];
        float4 o = make_float4(acc[i][0] * inv, acc[i][1] * inv,
                               acc[i][2] * inv, acc[i][3] * inv);
        *(float4*)&aout[(size_t)(b * NS + q0 + tr + i) * ND + hh * NHD + tc] = o;
    }
}

// ---------------------------------------------------------------------------
extern "C" void kernel_launch(void* const* d_in, const int* in_sizes, int n_in,
                              void* d_out, int out_size)
{
    const float* x     = (const float*)d_in[0];
    const float* Wqkv  = (const float*)d_in[1];
    const float* bqkv  = (const float*)d_in[2];
    const float* Wout  = (const float*)d_in[3];
    const float* bout  = (const float*)d_in[4];
    const int*   layer = (const int*)d_in[5];
    float* out = (float*)d_out;

    float *qkv, *attn;
    cudaGetSymbolAddress((void**)&qkv,  g_qkv);
    cudaGetSymbolAddress((void**)&attn, g_attn);

    const int attn_smem = (3 * 64 * PAD + 3 * 64) * (int)sizeof(float);  // 52992 B
    cudaFuncSetAttribute(attn_kernel, cudaFuncAttributeMaxDynamicSharedMemorySize, attn_smem);

    // 1) qkv = x @ Wqkv + bqkv
    sgemm_bias_kernel<<<dim3(NQKV / 128, NROWS / 128), 256>>>(x, Wqkv, bqkv, qkv,
                                                              NROWS, NQKV, ND);
    // 2) RoPE in-place on q,k
    rope_kernel<<<(NROWS * NH * 32) / 256, 256>>>(qkv, layer);
    // 3) banded attention
    attn_kernel<<<NB * NH * 32, 256, attn_smem>>>(qkv, attn, layer);
    // 4) out = attn @ Wout + bout
    sgemm_bias_kernel<<<dim3(ND / 128, NROWS / 128), 256>>>(attn, Wout, bout, out,
                                                            NROWS, ND, ND);
}